// round 9
// baseline (speedup 1.0000x reference)
#include <cuda_runtime.h>
#include <cstdint>

// Problem constants (fixed by the dataset)
#define BB 2
#define SS 2048
#define DD 1024
#define HH 16
#define DK 64
#define MM (BB * SS)  // 4096 rows

// Scratch (allocation-free rule: __device__ globals)
__device__ float g_q[(size_t)BB * HH * SS * DK];    // (B,H,S,DK)
__device__ float g_k[(size_t)BB * HH * SS * DK];
__device__ float g_v[(size_t)BB * HH * SS * DK];
__device__ float g_ctx[(size_t)BB * SS * DD];       // (B,S,D)

// ---------------------------------------------------------------------------
// helpers (baseline sm_80+ ISA — no 'a'-suffix features)
// ---------------------------------------------------------------------------
__device__ __forceinline__ uint32_t f2tf32(float x) {
    uint32_t r;
    asm("cvt.rna.tf32.f32 %0, %1;" : "=r"(r) : "f"(x));
    return r;
}

__device__ __forceinline__ float ex2(float x) {
    float r;
    asm("ex2.approx.ftz.f32 %0, %1;" : "=f"(r) : "f"(x));
    return r;
}

// pack two floats to bf16x2: lo half = first arg, hi half = second arg
__device__ __forceinline__ uint32_t pack_bf16x2(float lo, float hi) {
    uint32_t r;
    asm("cvt.rn.bf16x2.f32 %0, %1, %2;" : "=r"(r) : "f"(hi), "f"(lo));
    return r;
}
__device__ __forceinline__ float bf16lo_f(uint32_t w) {
    return __uint_as_float(w << 16);
}
__device__ __forceinline__ float bf16hi_f(uint32_t w) {
    return __uint_as_float(w & 0xFFFF0000u);
}

__device__ __forceinline__ void mma_tf32(float c[4], const uint32_t a[4],
                                         const uint32_t b[2]) {
    asm volatile(
        "mma.sync.aligned.m16n8k8.row.col.f32.tf32.tf32.f32 "
        "{%0,%1,%2,%3}, {%4,%5,%6,%7}, {%8,%9}, {%0,%1,%2,%3};"
        : "+f"(c[0]), "+f"(c[1]), "+f"(c[2]), "+f"(c[3])
        : "r"(a[0]), "r"(a[1]), "r"(a[2]), "r"(a[3]), "r"(b[0]), "r"(b[1]));
}

__device__ __forceinline__ void mma_bf16(float c[4], const uint32_t a[4],
                                         const uint32_t b[2]) {
    asm volatile(
        "mma.sync.aligned.m16n8k16.row.col.f32.bf16.bf16.f32 "
        "{%0,%1,%2,%3}, {%4,%5,%6,%7}, {%8,%9}, {%0,%1,%2,%3};"
        : "+f"(c[0]), "+f"(c[1]), "+f"(c[2]), "+f"(c[3])
        : "r"(a[0]), "r"(a[1]), "r"(a[2]), "r"(a[3]), "r"(b[0]), "r"(b[1]));
}

// ---------------------------------------------------------------------------
// tf32 mma.sync GEMM: C[128,128] = A[128,1024] * W[128,1024]^T + bias
// (unchanged from round 7)
// ---------------------------------------------------------------------------
#define MM_SMEM_BYTES 65536

template <bool SCATTER>
__device__ __forceinline__ void mm_core(const float* __restrict__ A,
                                        const float* __restrict__ W,
                                        const float* __restrict__ bias,
                                        float* __restrict__ out,
                                        int m0, int n0) {
    extern __shared__ char smem[];
    const int tid = threadIdx.x;
    const int lane = tid & 31;
    const int wid = tid >> 5;
    const int warp_m = wid & 1;
    const int warp_n = wid >> 1;

    float c[4][4][4];
#pragma unroll
    for (int i = 0; i < 4; i++)
#pragma unroll
        for (int j = 0; j < 4; j++)
#pragma unroll
            for (int e = 0; e < 4; e++) c[i][j][e] = 0.0f;

    const float* Abase = A + (size_t)m0 * DD;
    const float* Wbase = W + (size_t)n0 * DD;

    float4 av[4], bv[4];

#define STORE_STAGE(bufp)                                                     \
    do {                                                                      \
        char* sbA = smem + (bufp) * 32768;                                    \
        char* sbB = sbA + 16384;                                              \
        _Pragma("unroll") for (int i = 0; i < 4; i++) {                       \
            const int idx = tid + i * 256;                                    \
            const int row = idx >> 3, k4 = idx & 7;                           \
            const int kt = k4 >> 1, khi = k4 & 1;                             \
            const int mt = row >> 4, rm = row & 15;                           \
            const int slotA = kt * 8 + mt;                                    \
            const int elemA = (rm >> 3) + (khi << 1);                         \
            const int laneA0 = (rm & 7) * 4;                                  \
            const float ae[4] = {av[i].x, av[i].y, av[i].z, av[i].w};         \
            _Pragma("unroll") for (int e = 0; e < 4; e++)                     \
                *(uint32_t*)(sbA + ((slotA * 32 + ((laneA0 + e) ^ kt)) << 4)  \
                             + (elemA << 2)) = f2tf32(ae[e]);                 \
            const int nt = row >> 3, rn = row & 7;                            \
            const int slotB = kt * 16 + nt;                                   \
            const int laneB0 = rn * 4;                                        \
            const float be[4] = {bv[i].x, bv[i].y, bv[i].z, bv[i].w};         \
            _Pragma("unroll") for (int e = 0; e < 4; e++)                     \
                *(uint32_t*)(sbB + ((slotB * 32 + ((laneB0 + e) ^ kt)) << 3)  \
                             + (khi << 2)) = f2tf32(be[e]);                   \
        }                                                                     \
    } while (0)

#define LOAD_STAGE(c0)                                                        \
    do {                                                                      \
        _Pragma("unroll") for (int i = 0; i < 4; i++) {                       \
            const int idx = tid + i * 256;                                    \
            const int row = idx >> 3, k4 = idx & 7;                           \
            av[i] = *(const float4*)(Abase + (size_t)row * DD + (c0) + k4 * 4); \
            bv[i] = *(const float4*)(Wbase + (size_t)row * DD + (c0) + k4 * 4); \
        }                                                                     \
    } while (0)

    LOAD_STAGE(0);

    for (int ch = 0; ch < 32; ++ch) {
        const int buf = ch & 1;
        STORE_STAGE(buf);
        if (ch + 1 < 32) LOAD_STAGE((ch + 1) * 32);
        __syncthreads();

        const char* sbA = smem + buf * 32768;
        const char* sbB = sbA + 16384;
#pragma unroll
        for (int kt = 0; kt < 4; ++kt) {
            uint32_t af[4][4];
            uint32_t bf[4][2];
#pragma unroll
            for (int i = 0; i < 4; ++i) {
                const float4 v = *(const float4*)(sbA +
                    (((kt * 8 + warp_m * 4 + i) * 32 + (lane ^ kt)) << 4));
                af[i][0] = __float_as_uint(v.x);
                af[i][1] = __float_as_uint(v.y);
                af[i][2] = __float_as_uint(v.z);
                af[i][3] = __float_as_uint(v.w);
            }
#pragma unroll
            for (int j = 0; j < 4; ++j) {
                const float2 v = *(const float2*)(sbB +
                    (((kt * 16 + warp_n * 4 + j) * 32 + (lane ^ kt)) << 3));
                bf[j][0] = __float_as_uint(v.x);
                bf[j][1] = __float_as_uint(v.y);
            }
#pragma unroll
            for (int i = 0; i < 4; ++i)
#pragma unroll
                for (int j = 0; j < 4; ++j) mma_tf32(c[i][j], af[i], bf[j]);
        }
    }

#pragma unroll
    for (int i = 0; i < 4; ++i) {
        const int r0 = m0 + warp_m * 64 + i * 16 + (lane >> 2);
#pragma unroll
        for (int j = 0; j < 4; ++j) {
            const int cb = n0 + warp_n * 32 + j * 8 + 2 * (lane & 3);
            const float b0 = bias[cb], b1 = bias[cb + 1];
            float2 lo = {c[i][j][0] + b0, c[i][j][1] + b1};
            float2 hi = {c[i][j][2] + b0, c[i][j][3] + b1};
            if (SCATTER) {
                const int h = cb >> 6, d = cb & 63;
                const int bA = r0 >> 11, s0 = r0 & 2047;
                float* p0 = out + (((size_t)(bA * HH + h)) * SS + s0) * DK + d;
                *(float2*)p0 = lo;
                const int r1 = r0 + 8;
                const int bB = r1 >> 11, s1 = r1 & 2047;
                float* p1 = out + (((size_t)(bB * HH + h)) * SS + s1) * DK + d;
                *(float2*)p1 = hi;
            } else {
                *(float2*)(out + (size_t)r0 * DD + cb) = lo;
                *(float2*)(out + (size_t)(r0 + 8) * DD + cb) = hi;
            }
        }
    }
#undef STORE_STAGE
#undef LOAD_STAGE
}

__global__ void __launch_bounds__(256) qkv_mm_kernel(
    const float* __restrict__ x,
    const float* __restrict__ Wq, const float* __restrict__ bq,
    const float* __restrict__ Wk, const float* __restrict__ bk,
    const float* __restrict__ Wv, const float* __restrict__ bv) {
    const int z = blockIdx.z;
    const float* W = (z == 0) ? Wq : (z == 1) ? Wk : Wv;
    const float* bias = (z == 0) ? bq : (z == 1) ? bk : bv;
    float* out = (z == 0) ? g_q : (z == 1) ? g_k : g_v;
    mm_core<true>(x, W, bias, out, blockIdx.y * 128, blockIdx.x * 128);
}

__global__ void __launch_bounds__(256) oproj_mm_kernel(
    const float* __restrict__ Wo, const float* __restrict__ bo,
    float* __restrict__ out) {
    mm_core<false>(g_ctx, Wo, bo, out, blockIdx.y * 128, blockIdx.x * 128);
}

// ---------------------------------------------------------------------------
// Tensor-core flash attention, round 9:
//  - 2 CTAs/SM (__launch_bounds__(256,2)); K/V prefetch moved to after
//    softmax so staging regs don't overlap score regs (peak ~120 regs).
//  - QK bf16 3-term m16n8k16, PV tf32, log2-domain softmax.
//
// smem map (bytes):
//   buf b (b=0,1) at b*32768:
//     K : 32 slots x 32 lanes x 16B = 16384 {kh_b0,kh_b1,kl_b0,kl_b1} bf16x2
//     V : at +16384, 64 slots x 32 lanes x 8B = 16384 (tf32 pack)
//   mask: 65536 + b*256 (64 floats each)
//   P   : 66048, 8 warps x 16 rows x 68 floats
// ---------------------------------------------------------------------------
#define ATTN_SMEM 100864
#define A_BUFSTRIDE 32768
#define A_VOFF 16384
#define A_MSK 65536
#define A_PO 66048
#define PSTRIDE 68
#define PWARP 4352
#define QSCALE (0.125f * 1.44269504088896f)   // (1/sqrt(DK)) * log2(e)

__global__ void __launch_bounds__(256, 2) attn_kernel(const int* __restrict__ mask) {
    extern __shared__ char smem[];
    const int tid = threadIdx.x;
    const int lane = tid & 31;
    const int w = tid >> 5;
    const int gid = lane >> 2;
    const int tig = lane & 3;

    const int bh = blockIdx.y;
    const int b = bh >> 4;
    const int h = bh & 15;
    const int qs_base = blockIdx.x * 128 + w * 16;

    const float* qbase = g_q + (size_t)bh * SS * DK;
    const float* kbase = g_k + (size_t)bh * SS * DK;
    const float* vbase = g_v + (size_t)bh * SS * DK;

    // ---- Q fragments: bf16 hi/lo, m16n8k16 A layout, scale*log2e folded ----
    uint32_t qh[4][4], ql[4][4];
#pragma unroll
    for (int kt = 0; kt < 4; ++kt) {
#pragma unroll
        for (int r = 0; r < 4; ++r) {
            const int row = qs_base + gid + (r & 1) * 8;
            const int d = kt * 16 + 2 * tig + (r >> 1) * 8;
            const float2 qv = *(const float2*)(qbase + (size_t)row * DK + d);
            const float f0 = qv.x * QSCALE, f1 = qv.y * QSCALE;
            const uint32_t hw = pack_bf16x2(f0, f1);
            qh[kt][r] = hw;
            ql[kt][r] = pack_bf16x2(f0 - bf16lo_f(hw), f1 - bf16hi_f(hw));
        }
    }

    float o[8][4];
#pragma unroll
    for (int j = 0; j < 8; ++j)
#pragma unroll
        for (int e = 0; e < 4; ++e) o[j][e] = 0.0f;
    float m0 = -1e30f, m1 = -1e30f, l0 = 0.0f, l1 = 0.0f;

    char* Pw = smem + A_PO + w * PWARP;

    // staging registers (pipelined): tile t data loaded during tile t-1's PV
    float4 rk[4], rv[4];
    int rmask = 1;

    // prologue: LDG tile 0
#pragma unroll
    for (int i = 0; i < 4; ++i) {
        const int idx = tid + i * 256;
        const int row = idx >> 4, p4 = idx & 15;
        rk[i] = *(const float4*)(kbase + (size_t)row * DK + p4 * 4);
        rv[i] = *(const float4*)(vbase + (size_t)row * DK + p4 * 4);
    }
    if (tid < 64) rmask = mask[b * SS + tid];

    for (int t = 0; t < SS / 64; ++t) {
        const int buf = t & 1;
        char* kb = smem + buf * A_BUFSTRIDE;
        char* vb = kb + A_VOFF;

        // ---- STS staged tile t ----
#pragma unroll
        for (int i = 0; i < 4; ++i) {
            const int idx = tid + i * 256;
            const int row = idx >> 4, p4 = idx & 15;
            const float ke[4] = {rk[i].x, rk[i].y, rk[i].z, rk[i].w};
            const float ve[4] = {rv[i].x, rv[i].y, rv[i].z, rv[i].w};
            // K: bf16 hi/lo pairs
#pragma unroll
            for (int ep = 0; ep < 2; ++ep) {
                const int d0 = p4 * 4 + ep * 2;
                const int kt = d0 >> 4, dd = d0 & 15;
                const int reg = dd >> 3, quad = (dd >> 1) & 3;
                const int laneK = (((row & 7) * 4 + quad) ^ kt);
                char* base = kb + (((kt * 8 + (row >> 3)) * 32 + laneK) << 4)
                             + (reg << 2);
                const float f0 = ke[ep * 2], f1 = ke[ep * 2 + 1];
                const uint32_t hw = pack_bf16x2(f0, f1);
                *(uint32_t*)(base) = hw;
                *(uint32_t*)(base + 8) =
                    pack_bf16x2(f0 - bf16lo_f(hw), f1 - bf16hi_f(hw));
            }
            // V: tf32 pack
#pragma unroll
            for (int e = 0; e < 4; ++e) {
                const int d = p4 * 4 + e;
                const int dt = d >> 3;
                const int slotV = (row >> 3) * 8 + dt;
                const int laneV = (((d & 7) * 4 + (row & 3)) ^ (dt << 1));
                const int half = (row >> 2) & 1;
                *(uint32_t*)(vb + ((slotV * 32 + laneV) << 3) + (half << 2)) =
                    f2tf32(ve[e]);
            }
        }
        if (tid < 64)
            *(float*)(smem + A_MSK + buf * 256 + tid * 4) = rmask ? 0.0f : -1e9f;
        __syncthreads();

        // ---- scores (log2-domain): S = Q K^T via bf16 3-term ----
        float sc[8][4];
#pragma unroll
        for (int j = 0; j < 8; ++j)
#pragma unroll
            for (int e = 0; e < 4; ++e) sc[j][e] = 0.0f;
#pragma unroll
        for (int kt = 0; kt < 4; ++kt) {
#pragma unroll
            for (int j = 0; j < 8; ++j) {
                const uint4 k4v = *(const uint4*)(kb + (((kt * 8 + j) << 9) +
                                                       ((lane ^ kt) << 4)));
                uint32_t kh2[2] = {k4v.x, k4v.y};
                uint32_t kl2[2] = {k4v.z, k4v.w};
                mma_bf16(sc[j], qh[kt], kh2);
                mma_bf16(sc[j], qh[kt], kl2);
                mma_bf16(sc[j], ql[kt], kh2);
            }
        }

        // ---- mask, online softmax (log2-domain) ----
        const char* mbuf = smem + A_MSK + buf * 256;
#pragma unroll
        for (int j = 0; j < 8; ++j) {
            const float2 ma = *(const float2*)(mbuf + (j * 8 + 2 * tig) * 4);
            sc[j][0] += ma.x; sc[j][1] += ma.y;
            sc[j][2] += ma.x; sc[j][3] += ma.y;
        }
        float rm0 = -1e30f, rm1 = -1e30f;
#pragma unroll
        for (int j = 0; j < 8; ++j) {
            rm0 = fmaxf(rm0, fmaxf(sc[j][0], sc[j][1]));
            rm1 = fmaxf(rm1, fmaxf(sc[j][2], sc[j][3]));
        }
        rm0 = fmaxf(rm0, __shfl_xor_sync(0xFFFFFFFF, rm0, 1));
        rm0 = fmaxf(rm0, __shfl_xor_sync(0xFFFFFFFF, rm0, 2));
        rm1 = fmaxf(rm1, __shfl_xor_sync(0xFFFFFFFF, rm1, 1));
        rm1 = fmaxf(rm1, __shfl_xor_sync(0xFFFFFFFF, rm1, 2));
        const float nm0 = fmaxf(m0, rm0), nm1 = fmaxf(m1, rm1);
        const float c0 = ex2(m0 - nm0), c1 = ex2(m1 - nm1);
        m0 = nm0; m1 = nm1;
        l0 *= c0; l1 *= c1;
#pragma unroll
        for (int j = 0; j < 8; ++j) {
            o[j][0] *= c0; o[j][1] *= c0;
            o[j][2] *= c1; o[j][3] *= c1;
        }
        float s0 = 0.0f, s1 = 0.0f;
#pragma unroll
        for (int j = 0; j < 8; ++j) {
            const float p0 = ex2(sc[j][0] - nm0);
            const float p1 = ex2(sc[j][1] - nm0);
            const float p2 = ex2(sc[j][2] - nm1);
            const float p3 = ex2(sc[j][3] - nm1);
            s0 += p0 + p1; s1 += p2 + p3;
            const int cb = j * 8 + 2 * tig;
            float2 v0 = {__uint_as_float(f2tf32(p0)), __uint_as_float(f2tf32(p1))};
            float2 v1 = {__uint_as_float(f2tf32(p2)), __uint_as_float(f2tf32(p3))};
            *(float2*)(Pw + (gid * PSTRIDE + cb) * 4) = v0;
            *(float2*)(Pw + ((gid + 8) * PSTRIDE + cb) * 4) = v1;
        }
        l0 += s0; l1 += s1;

        // ---- LDG tile t+1 (after softmax: regs don't overlap sc; latency
        //      covered by the PV loop below; K/V are L2-resident) ----
        if (t + 1 < SS / 64) {
            const int key0n = (t + 1) * 64;
#pragma unroll
            for (int i = 0; i < 4; ++i) {
                const int idx = tid + i * 256;
                const int row = idx >> 4, p4 = idx & 15;
                rk[i] = *(const float4*)(kbase + (size_t)(key0n + row) * DK + p4 * 4);
                rv[i] = *(const float4*)(vbase + (size_t)(key0n + row) * DK + p4 * 4);
            }
            if (tid < 64) rmask = mask[b * SS + key0n + tid];
        }
        __syncwarp();

        // ---- O += P V (tf32) ----
#pragma unroll
        for (int kk = 0; kk < 8; ++kk) {
            uint32_t pa[4];
            pa[0] = *(const uint32_t*)(Pw + (gid * PSTRIDE + kk * 8 + tig) * 4);
            pa[1] = *(const uint32_t*)(Pw + ((gid + 8) * PSTRIDE + kk * 8 + tig) * 4);
            pa[2] = *(const uint32_t*)(Pw + (gid * PSTRIDE + kk * 8 + tig + 4) * 4);
            pa[3] = *(const uint32_t*)(Pw + ((gid + 8) * PSTRIDE + kk * 8 + tig + 4) * 4);
#pragma unroll
            for (int j = 0; j < 8; ++j) {
                uint32_t bvf[2];
                const uint2 bv2 = *(const uint2*)(vb +
                    (((kk * 8 + j) * 32 + (lane ^ (j << 1))) << 3));
                bvf[0] = bv2.x; bvf[1] = bv2.y;
                mma_tf32(o[j], pa, bvf);
            }
        }
        __syncwarp();
    }

    // ---- finalize ----
    float lt0 = l0, lt1 = l1;
    lt0 += __shfl_xor_sync(0xFFFFFFFF, lt0, 1);
    lt0 += __shfl_xor_sync(0xFFFFFFFF, lt0, 2);
    lt1 += __shfl_xor_sync(0xFFFFFFFF, lt1, 1);
    lt1 += __shfl_xor_sync(0xFFFFFFFF, lt1, 2);
    const float inv0 = 1.0f / lt0, inv1 = 1.0f / lt1;

    const int r0 = qs_base + gid, r1 = r0 + 8;
    float* o0 = g_ctx + ((size_t)(b * SS + r0)) * DD + h * DK;
    float* o1 = g_ctx + ((size_t)(b * SS + r1)) * DD + h * DK;
#pragma unroll
    for (int j = 0; j < 8; ++j) {
        const int cb = j * 8 + 2 * tig;
        float2 v0 = {o[j][0] * inv0, o[j][1] * inv0};
        float2 v1 = {o[j][2] * inv1, o[j][3] * inv1};
        *(float2*)(o0 + cb) = v0;
        *(float2*)(o1 + cb) = v1;
    }
}

// ---------------------------------------------------------------------------
// Inputs (metadata order): x, mask, Wq, bq, Wk, bk, Wv, bv, Wo, bo
// ---------------------------------------------------------------------------
extern "C" void kernel_launch(void* const* d_in, const int* in_sizes, int n_in,
                              void* d_out, int out_size) {
    const float* x  = (const float*)d_in[0];
    const int*   mk = (const int*)d_in[1];
    const float* Wq = (const float*)d_in[2];
    const float* bq = (const float*)d_in[3];
    const float* Wk = (const float*)d_in[4];
    const float* bk = (const float*)d_in[5];
    const float* Wv = (const float*)d_in[6];
    const float* bv = (const float*)d_in[7];
    const float* Wo = (const float*)d_in[8];
    const float* bo = (const float*)d_in[9];
    float* out = (float*)d_out;

    static bool configured = false;
    if (!configured) {
        cudaFuncSetAttribute(qkv_mm_kernel,
                             cudaFuncAttributeMaxDynamicSharedMemorySize,
                             MM_SMEM_BYTES);
        cudaFuncSetAttribute(oproj_mm_kernel,
                             cudaFuncAttributeMaxDynamicSharedMemorySize,
                             MM_SMEM_BYTES);
        cudaFuncSetAttribute(attn_kernel,
                             cudaFuncAttributeMaxDynamicSharedMemorySize,
                             ATTN_SMEM);
        configured = true;
    }

    // QKV projections (tf32 mma.sync), scattered to (B,H,S,DK)
    qkv_mm_kernel<<<dim3(DD / 128, MM / 128, 3), 256, MM_SMEM_BYTES>>>(
        x, Wq, bq, Wk, bk, Wv, bv);

    // Tensor-core flash attention (bf16 QK, tf32 PV, 2 CTAs/SM)
    attn_kernel<<<dim3(SS / 128, BB * HH), 256, ATTN_SMEM>>>(mk);

    // Output projection (tf32 mma.sync) -> d_out
    oproj_mm_kernel<<<dim3(DD / 128, MM / 128), 256, MM_SMEM_BYTES>>>(Wo, bo, out);
}

// round 10
// speedup vs baseline: 1.2954x; 1.2954x over previous
#include <cuda_runtime.h>
#include <cstdint>

// Problem constants (fixed by the dataset)
#define BB 2
#define SS 2048
#define DD 1024
#define HH 16
#define DK 64
#define MM (BB * SS)  // 4096 rows

// Scratch (allocation-free rule: __device__ globals)
__device__ float g_q[(size_t)BB * HH * SS * DK];    // (B,H,S,DK)
__device__ float g_k[(size_t)BB * HH * SS * DK];
__device__ float g_v[(size_t)BB * HH * SS * DK];
__device__ float g_ctx[(size_t)BB * SS * DD];       // (B,S,D)

// ---------------------------------------------------------------------------
// helpers (baseline sm_80+ ISA — no 'a'-suffix features)
// ---------------------------------------------------------------------------
__device__ __forceinline__ uint32_t f2tf32(float x) {
    uint32_t r;
    asm("cvt.rna.tf32.f32 %0, %1;" : "=r"(r) : "f"(x));
    return r;
}

__device__ __forceinline__ float ex2(float x) {
    float r;
    asm("ex2.approx.ftz.f32 %0, %1;" : "=f"(r) : "f"(x));
    return r;
}

// pack two floats to bf16x2 / f16x2: lo half = first arg, hi half = second
__device__ __forceinline__ uint32_t pack_bf16x2(float lo, float hi) {
    uint32_t r;
    asm("cvt.rn.bf16x2.f32 %0, %1, %2;" : "=r"(r) : "f"(hi), "f"(lo));
    return r;
}
__device__ __forceinline__ uint32_t pack_f16x2(float lo, float hi) {
    uint32_t r;
    asm("cvt.rn.f16x2.f32 %0, %1, %2;" : "=r"(r) : "f"(hi), "f"(lo));
    return r;
}
__device__ __forceinline__ float bf16lo_f(uint32_t w) {
    return __uint_as_float(w << 16);
}
__device__ __forceinline__ float bf16hi_f(uint32_t w) {
    return __uint_as_float(w & 0xFFFF0000u);
}

__device__ __forceinline__ void mma_tf32(float c[4], const uint32_t a[4],
                                         const uint32_t b[2]) {
    asm volatile(
        "mma.sync.aligned.m16n8k8.row.col.f32.tf32.tf32.f32 "
        "{%0,%1,%2,%3}, {%4,%5,%6,%7}, {%8,%9}, {%0,%1,%2,%3};"
        : "+f"(c[0]), "+f"(c[1]), "+f"(c[2]), "+f"(c[3])
        : "r"(a[0]), "r"(a[1]), "r"(a[2]), "r"(a[3]), "r"(b[0]), "r"(b[1]));
}

__device__ __forceinline__ void mma_bf16(float c[4], const uint32_t a[4],
                                         const uint32_t b[2]) {
    asm volatile(
        "mma.sync.aligned.m16n8k16.row.col.f32.bf16.bf16.f32 "
        "{%0,%1,%2,%3}, {%4,%5,%6,%7}, {%8,%9}, {%0,%1,%2,%3};"
        : "+f"(c[0]), "+f"(c[1]), "+f"(c[2]), "+f"(c[3])
        : "r"(a[0]), "r"(a[1]), "r"(a[2]), "r"(a[3]), "r"(b[0]), "r"(b[1]));
}

__device__ __forceinline__ void mma_fp16(float c[4], const uint32_t a[4],
                                         const uint32_t b[2]) {
    asm volatile(
        "mma.sync.aligned.m16n8k16.row.col.f32.f16.f16.f32 "
        "{%0,%1,%2,%3}, {%4,%5,%6,%7}, {%8,%9}, {%0,%1,%2,%3};"
        : "+f"(c[0]), "+f"(c[1]), "+f"(c[2]), "+f"(c[3])
        : "r"(a[0]), "r"(a[1]), "r"(a[2]), "r"(a[3]), "r"(b[0]), "r"(b[1]));
}

// ---------------------------------------------------------------------------
// fp16 mma.sync GEMM: C[128,128] = A[128,1024] * W[128,1024]^T + bias
// 8 warps (2 m x 4 n), warp tile 64x32, BK=32 (2 k16 steps), double-buffered
// smem, single __syncthreads per chunk. Fragment-packed half2 smem with
// XOR-kt lane swizzle.
//
// Buf layout (16KB per buf, 2 bufs):
//   A: 16 slots (kt*8+mt) x 32 lanes x 16B {a0,a1,a2,a3}      = 8192 B
//   B: at +8192, 32 slots (kt*16+nt) x 32 lanes x 8B {b0,b1}  = 8192 B
// ---------------------------------------------------------------------------
#define MM_SMEM_BYTES 32768

template <bool SCATTER>
__device__ __forceinline__ void mm_core(const float* __restrict__ A,
                                        const float* __restrict__ W,
                                        const float* __restrict__ bias,
                                        float* __restrict__ out,
                                        int m0, int n0) {
    extern __shared__ char smem[];
    const int tid = threadIdx.x;
    const int lane = tid & 31;
    const int wid = tid >> 5;
    const int warp_m = wid & 1;
    const int warp_n = wid >> 1;

    float c[4][4][4];
#pragma unroll
    for (int i = 0; i < 4; i++)
#pragma unroll
        for (int j = 0; j < 4; j++)
#pragma unroll
            for (int e = 0; e < 4; e++) c[i][j][e] = 0.0f;

    const float* Abase = A + (size_t)m0 * DD;
    const float* Wbase = W + (size_t)n0 * DD;

    float4 av[4], bv[4];

    // Each float4 (row, k=4*k4..4*k4+3) = two half2 pairs P0=2*k4, P1=P0+1.
    // Both pairs share kt = k4>>2 and the a-reg/b-reg index (p0 is even).
#define STORE_STAGE(bufp)                                                     \
    do {                                                                      \
        char* sbA = smem + (bufp) * 16384;                                    \
        char* sbB = sbA + 8192;                                               \
        _Pragma("unroll") for (int i = 0; i < 4; i++) {                       \
            const int idx = tid + i * 256;                                    \
            const int row = idx >> 3, k4 = idx & 7;                           \
            const int kt = k4 >> 2;                                           \
            const int p0 = (k4 & 3) * 2;                                      \
            const uint32_t w0 = pack_f16x2(av[i].x, av[i].y);                 \
            const uint32_t w1 = pack_f16x2(av[i].z, av[i].w);                 \
            const uint32_t u0 = pack_f16x2(bv[i].x, bv[i].y);                 \
            const uint32_t u1 = pack_f16x2(bv[i].z, bv[i].w);                 \
            { /* A pack */                                                    \
                const int rm = row & 15, mt = row >> 4;                       \
                const int aidx = (rm >> 3) + ((p0 >> 2) << 1);                \
                const int slotA = kt * 8 + mt;                                \
                const int lb = (rm & 7) * 4 + (p0 & 3);                       \
                *(uint32_t*)(sbA + ((slotA * 32 + (lb ^ kt)) << 4)            \
                             + (aidx << 2)) = w0;                             \
                *(uint32_t*)(sbA + ((slotA * 32 + ((lb + 1) ^ kt)) << 4)      \
                             + (aidx << 2)) = w1;                             \
            }                                                                 \
            { /* B pack */                                                    \
                const int rn = row & 7, nt = row >> 3;                        \
                const int bidx = p0 >> 2;                                     \
                const int slotB = kt * 16 + nt;                               \
                const int lb = rn * 4 + (p0 & 3);                             \
                *(uint32_t*)(sbB + ((slotB * 32 + (lb ^ kt)) << 3)            \
                             + (bidx << 2)) = u0;                             \
                *(uint32_t*)(sbB + ((slotB * 32 + ((lb + 1) ^ kt)) << 3)      \
                             + (bidx << 2)) = u1;                             \
            }                                                                 \
        }                                                                     \
    } while (0)

#define LOAD_STAGE(c0)                                                        \
    do {                                                                      \
        _Pragma("unroll") for (int i = 0; i < 4; i++) {                       \
            const int idx = tid + i * 256;                                    \
            const int row = idx >> 3, k4 = idx & 7;                           \
            av[i] = *(const float4*)(Abase + (size_t)row * DD + (c0) + k4 * 4); \
            bv[i] = *(const float4*)(Wbase + (size_t)row * DD + (c0) + k4 * 4); \
        }                                                                     \
    } while (0)

    LOAD_STAGE(0);

    for (int ch = 0; ch < 32; ++ch) {
        const int buf = ch & 1;
        STORE_STAGE(buf);
        if (ch + 1 < 32) LOAD_STAGE((ch + 1) * 32);
        __syncthreads();

        const char* sbA = smem + buf * 16384;
        const char* sbB = sbA + 8192;
#pragma unroll
        for (int kt = 0; kt < 2; ++kt) {
            uint32_t af[4][4];
            uint32_t bf[4][2];
#pragma unroll
            for (int i = 0; i < 4; ++i) {
                const uint4 v = *(const uint4*)(sbA +
                    (((kt * 8 + warp_m * 4 + i) * 32 + (lane ^ kt)) << 4));
                af[i][0] = v.x; af[i][1] = v.y;
                af[i][2] = v.z; af[i][3] = v.w;
            }
#pragma unroll
            for (int j = 0; j < 4; ++j) {
                const uint2 v = *(const uint2*)(sbB +
                    (((kt * 16 + warp_n * 4 + j) * 32 + (lane ^ kt)) << 3));
                bf[j][0] = v.x; bf[j][1] = v.y;
            }
#pragma unroll
            for (int i = 0; i < 4; ++i)
#pragma unroll
                for (int j = 0; j < 4; ++j) mma_fp16(c[i][j], af[i], bf[j]);
        }
    }

#pragma unroll
    for (int i = 0; i < 4; ++i) {
        const int r0 = m0 + warp_m * 64 + i * 16 + (lane >> 2);
#pragma unroll
        for (int j = 0; j < 4; ++j) {
            const int cb = n0 + warp_n * 32 + j * 8 + 2 * (lane & 3);
            const float b0 = bias[cb], b1 = bias[cb + 1];
            float2 lo = {c[i][j][0] + b0, c[i][j][1] + b1};
            float2 hi = {c[i][j][2] + b0, c[i][j][3] + b1};
            if (SCATTER) {
                const int h = cb >> 6, d = cb & 63;
                const int bA = r0 >> 11, s0 = r0 & 2047;
                float* p0 = out + (((size_t)(bA * HH + h)) * SS + s0) * DK + d;
                *(float2*)p0 = lo;
                const int r1 = r0 + 8;
                const int bB = r1 >> 11, s1 = r1 & 2047;
                float* p1 = out + (((size_t)(bB * HH + h)) * SS + s1) * DK + d;
                *(float2*)p1 = hi;
            } else {
                *(float2*)(out + (size_t)r0 * DD + cb) = lo;
                *(float2*)(out + (size_t)(r0 + 8) * DD + cb) = hi;
            }
        }
    }
#undef STORE_STAGE
#undef LOAD_STAGE
}

__global__ void __launch_bounds__(256) qkv_mm_kernel(
    const float* __restrict__ x,
    const float* __restrict__ Wq, const float* __restrict__ bq,
    const float* __restrict__ Wk, const float* __restrict__ bk,
    const float* __restrict__ Wv, const float* __restrict__ bv) {
    const int z = blockIdx.z;
    const float* W = (z == 0) ? Wq : (z == 1) ? Wk : Wv;
    const float* bias = (z == 0) ? bq : (z == 1) ? bk : bv;
    float* out = (z == 0) ? g_q : (z == 1) ? g_k : g_v;
    mm_core<true>(x, W, bias, out, blockIdx.y * 128, blockIdx.x * 128);
}

__global__ void __launch_bounds__(256) oproj_mm_kernel(
    const float* __restrict__ Wo, const float* __restrict__ bo,
    float* __restrict__ out) {
    mm_core<false>(g_ctx, Wo, bo, out, blockIdx.y * 128, blockIdx.x * 128);
}

// ---------------------------------------------------------------------------
// Tensor-core flash attention (round-8 form: 1 CTA/SM, prefetch before sync).
// QK bf16 3-term m16n8k16, PV tf32, log2-domain softmax.
//
// smem map (bytes):
//   buf b (b=0,1) at b*32768:
//     K : 32 slots x 32 lanes x 16B = 16384 {kh_b0,kh_b1,kl_b0,kl_b1} bf16x2
//     V : at +16384, 64 slots x 32 lanes x 8B = 16384 (tf32 pack)
//   mask: 65536 + b*256 (64 floats each)
//   P   : 66048, 8 warps x 16 rows x 68 floats
// ---------------------------------------------------------------------------
#define ATTN_SMEM 100864
#define A_BUFSTRIDE 32768
#define A_VOFF 16384
#define A_MSK 65536
#define A_PO 66048
#define PSTRIDE 68
#define PWARP 4352
#define QSCALE (0.125f * 1.44269504088896f)   // (1/sqrt(DK)) * log2(e)

__global__ void __launch_bounds__(256, 1) attn_kernel(const int* __restrict__ mask) {
    extern __shared__ char smem[];
    const int tid = threadIdx.x;
    const int lane = tid & 31;
    const int w = tid >> 5;
    const int gid = lane >> 2;
    const int tig = lane & 3;

    const int bh = blockIdx.y;
    const int b = bh >> 4;
    const int h = bh & 15;
    const int qs_base = blockIdx.x * 128 + w * 16;

    const float* qbase = g_q + (size_t)bh * SS * DK;
    const float* kbase = g_k + (size_t)bh * SS * DK;
    const float* vbase = g_v + (size_t)bh * SS * DK;

    // ---- Q fragments: bf16 hi/lo, m16n8k16 A layout, scale*log2e folded ----
    uint32_t qh[4][4], ql[4][4];
#pragma unroll
    for (int kt = 0; kt < 4; ++kt) {
#pragma unroll
        for (int r = 0; r < 4; ++r) {
            const int row = qs_base + gid + (r & 1) * 8;
            const int d = kt * 16 + 2 * tig + (r >> 1) * 8;
            const float2 qv = *(const float2*)(qbase + (size_t)row * DK + d);
            const float f0 = qv.x * QSCALE, f1 = qv.y * QSCALE;
            const uint32_t hw = pack_bf16x2(f0, f1);
            qh[kt][r] = hw;
            ql[kt][r] = pack_bf16x2(f0 - bf16lo_f(hw), f1 - bf16hi_f(hw));
        }
    }

    float o[8][4];
#pragma unroll
    for (int j = 0; j < 8; ++j)
#pragma unroll
        for (int e = 0; e < 4; ++e) o[j][e] = 0.0f;
    float m0 = -1e30f, m1 = -1e30f, l0 = 0.0f, l1 = 0.0f;

    char* Pw = smem + A_PO + w * PWARP;

    // staging registers (pipelined): tile t data loaded during tile t-1
    float4 rk[4], rv[4];
    int rmask = 1;

    // prologue: LDG tile 0
#pragma unroll
    for (int i = 0; i < 4; ++i) {
        const int idx = tid + i * 256;
        const int row = idx >> 4, p4 = idx & 15;
        rk[i] = *(const float4*)(kbase + (size_t)row * DK + p4 * 4);
        rv[i] = *(const float4*)(vbase + (size_t)row * DK + p4 * 4);
    }
    if (tid < 64) rmask = mask[b * SS + tid];

    for (int t = 0; t < SS / 64; ++t) {
        const int buf = t & 1;
        char* kb = smem + buf * A_BUFSTRIDE;
        char* vb = kb + A_VOFF;

        // ---- STS staged tile t ----
#pragma unroll
        for (int i = 0; i < 4; ++i) {
            const int idx = tid + i * 256;
            const int row = idx >> 4, p4 = idx & 15;
            const float ke[4] = {rk[i].x, rk[i].y, rk[i].z, rk[i].w};
            const float ve[4] = {rv[i].x, rv[i].y, rv[i].z, rv[i].w};
            // K: bf16 hi/lo pairs
#pragma unroll
            for (int ep = 0; ep < 2; ++ep) {
                const int d0 = p4 * 4 + ep * 2;
                const int kt = d0 >> 4, dd = d0 & 15;
                const int reg = dd >> 3, quad = (dd >> 1) & 3;
                const int laneK = (((row & 7) * 4 + quad) ^ kt);
                char* base = kb + (((kt * 8 + (row >> 3)) * 32 + laneK) << 4)
                             + (reg << 2);
                const float f0 = ke[ep * 2], f1 = ke[ep * 2 + 1];
                const uint32_t hw = pack_bf16x2(f0, f1);
                *(uint32_t*)(base) = hw;
                *(uint32_t*)(base + 8) =
                    pack_bf16x2(f0 - bf16lo_f(hw), f1 - bf16hi_f(hw));
            }
            // V: tf32 pack
#pragma unroll
            for (int e = 0; e < 4; ++e) {
                const int d = p4 * 4 + e;
                const int dt = d >> 3;
                const int slotV = (row >> 3) * 8 + dt;
                const int laneV = (((d & 7) * 4 + (row & 3)) ^ (dt << 1));
                const int half = (row >> 2) & 1;
                *(uint32_t*)(vb + ((slotV * 32 + laneV) << 3) + (half << 2)) =
                    f2tf32(ve[e]);
            }
        }
        if (tid < 64)
            *(float*)(smem + A_MSK + buf * 256 + tid * 4) = rmask ? 0.0f : -1e9f;

        // ---- LDG tile t+1 (latency hidden under compute of tile t) ----
        if (t + 1 < SS / 64) {
            const int key0n = (t + 1) * 64;
#pragma unroll
            for (int i = 0; i < 4; ++i) {
                const int idx = tid + i * 256;
                const int row = idx >> 4, p4 = idx & 15;
                rk[i] = *(const float4*)(kbase + (size_t)(key0n + row) * DK + p4 * 4);
                rv[i] = *(const float4*)(vbase + (size_t)(key0n + row) * DK + p4 * 4);
            }
            if (tid < 64) rmask = mask[b * SS + key0n + tid];
        }
        __syncthreads();

        // ---- scores (log2-domain): S = Q K^T via bf16 3-term ----
        float sc[8][4];
#pragma unroll
        for (int j = 0; j < 8; ++j)
#pragma unroll
            for (int e = 0; e < 4; ++e) sc[j][e] = 0.0f;
#pragma unroll
        for (int kt = 0; kt < 4; ++kt) {
#pragma unroll
            for (int j = 0; j < 8; ++j) {
                const uint4 k4v = *(const uint4*)(kb + (((kt * 8 + j) << 9) +
                                                       ((lane ^ kt) << 4)));
                uint32_t kh2[2] = {k4v.x, k4v.y};
                uint32_t kl2[2] = {k4v.z, k4v.w};
                mma_bf16(sc[j], qh[kt], kh2);
                mma_bf16(sc[j], qh[kt], kl2);
                mma_bf16(sc[j], ql[kt], kh2);
            }
        }

        // ---- mask, online softmax (log2-domain) ----
        const char* mbuf = smem + A_MSK + buf * 256;
#pragma unroll
        for (int j = 0; j < 8; ++j) {
            const float2 ma = *(const float2*)(mbuf + (j * 8 + 2 * tig) * 4);
            sc[j][0] += ma.x; sc[j][1] += ma.y;
            sc[j][2] += ma.x; sc[j][3] += ma.y;
        }
        float rm0 = -1e30f, rm1 = -1e30f;
#pragma unroll
        for (int j = 0; j < 8; ++j) {
            rm0 = fmaxf(rm0, fmaxf(sc[j][0], sc[j][1]));
            rm1 = fmaxf(rm1, fmaxf(sc[j][2], sc[j][3]));
        }
        rm0 = fmaxf(rm0, __shfl_xor_sync(0xFFFFFFFF, rm0, 1));
        rm0 = fmaxf(rm0, __shfl_xor_sync(0xFFFFFFFF, rm0, 2));
        rm1 = fmaxf(rm1, __shfl_xor_sync(0xFFFFFFFF, rm1, 1));
        rm1 = fmaxf(rm1, __shfl_xor_sync(0xFFFFFFFF, rm1, 2));
        const float nm0 = fmaxf(m0, rm0), nm1 = fmaxf(m1, rm1);
        const float c0 = ex2(m0 - nm0), c1 = ex2(m1 - nm1);
        m0 = nm0; m1 = nm1;
        l0 *= c0; l1 *= c1;
#pragma unroll
        for (int j = 0; j < 8; ++j) {
            o[j][0] *= c0; o[j][1] *= c0;
            o[j][2] *= c1; o[j][3] *= c1;
        }
        float s0 = 0.0f, s1 = 0.0f;
#pragma unroll
        for (int j = 0; j < 8; ++j) {
            const float p0 = ex2(sc[j][0] - nm0);
            const float p1 = ex2(sc[j][1] - nm0);
            const float p2 = ex2(sc[j][2] - nm1);
            const float p3 = ex2(sc[j][3] - nm1);
            s0 += p0 + p1; s1 += p2 + p3;
            const int cb = j * 8 + 2 * tig;
            float2 v0 = {__uint_as_float(f2tf32(p0)), __uint_as_float(f2tf32(p1))};
            float2 v1 = {__uint_as_float(f2tf32(p2)), __uint_as_float(f2tf32(p3))};
            *(float2*)(Pw + (gid * PSTRIDE + cb) * 4) = v0;
            *(float2*)(Pw + ((gid + 8) * PSTRIDE + cb) * 4) = v1;
        }
        l0 += s0; l1 += s1;
        __syncwarp();

        // ---- O += P V (tf32) ----
#pragma unroll
        for (int kk = 0; kk < 8; ++kk) {
            uint32_t pa[4];
            pa[0] = *(const uint32_t*)(Pw + (gid * PSTRIDE + kk * 8 + tig) * 4);
            pa[1] = *(const uint32_t*)(Pw + ((gid + 8) * PSTRIDE + kk * 8 + tig) * 4);
            pa[2] = *(const uint32_t*)(Pw + (gid * PSTRIDE + kk * 8 + tig + 4) * 4);
            pa[3] = *(const uint32_t*)(Pw + ((gid + 8) * PSTRIDE + kk * 8 + tig + 4) * 4);
#pragma unroll
            for (int j = 0; j < 8; ++j) {
                uint32_t bvf[2];
                const uint2 bv2 = *(const uint2*)(vb +
                    (((kk * 8 + j) * 32 + (lane ^ (j << 1))) << 3));
                bvf[0] = bv2.x; bvf[1] = bv2.y;
                mma_tf32(o[j], pa, bvf);
            }
        }
        __syncwarp();
    }

    // ---- finalize ----
    float lt0 = l0, lt1 = l1;
    lt0 += __shfl_xor_sync(0xFFFFFFFF, lt0, 1);
    lt0 += __shfl_xor_sync(0xFFFFFFFF, lt0, 2);
    lt1 += __shfl_xor_sync(0xFFFFFFFF, lt1, 1);
    lt1 += __shfl_xor_sync(0xFFFFFFFF, lt1, 2);
    const float inv0 = 1.0f / lt0, inv1 = 1.0f / lt1;

    const int r0 = qs_base + gid, r1 = r0 + 8;
    float* o0 = g_ctx + ((size_t)(b * SS + r0)) * DD + h * DK;
    float* o1 = g_ctx + ((size_t)(b * SS + r1)) * DD + h * DK;
#pragma unroll
    for (int j = 0; j < 8; ++j) {
        const int cb = j * 8 + 2 * tig;
        float2 v0 = {o[j][0] * inv0, o[j][1] * inv0};
        float2 v1 = {o[j][2] * inv1, o[j][3] * inv1};
        *(float2*)(o0 + cb) = v0;
        *(float2*)(o1 + cb) = v1;
    }
}

// ---------------------------------------------------------------------------
// Inputs (metadata order): x, mask, Wq, bq, Wk, bk, Wv, bv, Wo, bo
// ---------------------------------------------------------------------------
extern "C" void kernel_launch(void* const* d_in, const int* in_sizes, int n_in,
                              void* d_out, int out_size) {
    const float* x  = (const float*)d_in[0];
    const int*   mk = (const int*)d_in[1];
    const float* Wq = (const float*)d_in[2];
    const float* bq = (const float*)d_in[3];
    const float* Wk = (const float*)d_in[4];
    const float* bk = (const float*)d_in[5];
    const float* Wv = (const float*)d_in[6];
    const float* bv = (const float*)d_in[7];
    const float* Wo = (const float*)d_in[8];
    const float* bo = (const float*)d_in[9];
    float* out = (float*)d_out;

    static bool configured = false;
    if (!configured) {
        cudaFuncSetAttribute(qkv_mm_kernel,
                             cudaFuncAttributeMaxDynamicSharedMemorySize,
                             MM_SMEM_BYTES);
        cudaFuncSetAttribute(oproj_mm_kernel,
                             cudaFuncAttributeMaxDynamicSharedMemorySize,
                             MM_SMEM_BYTES);
        cudaFuncSetAttribute(attn_kernel,
                             cudaFuncAttributeMaxDynamicSharedMemorySize,
                             ATTN_SMEM);
        configured = true;
    }

    // QKV projections (fp16 mma.sync, fp32 accumulate), scattered to (B,H,S,DK)
    qkv_mm_kernel<<<dim3(DD / 128, MM / 128, 3), 256, MM_SMEM_BYTES>>>(
        x, Wq, bq, Wk, bk, Wv, bv);

    // Tensor-core flash attention (bf16 QK, tf32 PV)
    attn_kernel<<<dim3(SS / 128, BB * HH), 256, ATTN_SMEM>>>(mk);

    // Output projection (fp16 mma.sync) -> d_out
    oproj_mm_kernel<<<dim3(DD / 128, MM / 128), 256, MM_SMEM_BYTES>>>(Wo, bo, out);
}

// round 11
// speedup vs baseline: 1.6229x; 1.2528x over previous
#include <cuda_runtime.h>
#include <cstdint>

// Problem constants (fixed by the dataset)
#define BB 2
#define SS 2048
#define DD 1024
#define HH 16
#define DK 64
#define MM (BB * SS)  // 4096 rows

// Scratch (allocation-free rule: __device__ globals)
__device__ float g_q[(size_t)BB * HH * SS * DK];    // (B,H,S,DK)
__device__ float g_k[(size_t)BB * HH * SS * DK];
__device__ float g_v[(size_t)BB * HH * SS * DK];
__device__ float g_ctx[(size_t)BB * SS * DD];       // (B,S,D)

// ---------------------------------------------------------------------------
// helpers (baseline sm_80+ ISA — no 'a'-suffix features)
// ---------------------------------------------------------------------------
__device__ __forceinline__ float ex2(float x) {
    float r;
    asm("ex2.approx.ftz.f32 %0, %1;" : "=f"(r) : "f"(x));
    return r;
}

// pack two floats to bf16x2 / f16x2: lo half = first arg, hi half = second
__device__ __forceinline__ uint32_t pack_bf16x2(float lo, float hi) {
    uint32_t r;
    asm("cvt.rn.bf16x2.f32 %0, %1, %2;" : "=r"(r) : "f"(hi), "f"(lo));
    return r;
}
__device__ __forceinline__ uint32_t pack_f16x2(float lo, float hi) {
    uint32_t r;
    asm("cvt.rn.f16x2.f32 %0, %1, %2;" : "=r"(r) : "f"(hi), "f"(lo));
    return r;
}
__device__ __forceinline__ float bf16lo_f(uint32_t w) {
    return __uint_as_float(w << 16);
}
__device__ __forceinline__ float bf16hi_f(uint32_t w) {
    return __uint_as_float(w & 0xFFFF0000u);
}

__device__ __forceinline__ void mma_bf16(float c[4], const uint32_t a[4],
                                         const uint32_t b[2]) {
    asm volatile(
        "mma.sync.aligned.m16n8k16.row.col.f32.bf16.bf16.f32 "
        "{%0,%1,%2,%3}, {%4,%5,%6,%7}, {%8,%9}, {%0,%1,%2,%3};"
        : "+f"(c[0]), "+f"(c[1]), "+f"(c[2]), "+f"(c[3])
        : "r"(a[0]), "r"(a[1]), "r"(a[2]), "r"(a[3]), "r"(b[0]), "r"(b[1]));
}

__device__ __forceinline__ void mma_fp16(float c[4], const uint32_t a[4],
                                         const uint32_t b[2]) {
    asm volatile(
        "mma.sync.aligned.m16n8k16.row.col.f32.f16.f16.f32 "
        "{%0,%1,%2,%3}, {%4,%5,%6,%7}, {%8,%9}, {%0,%1,%2,%3};"
        : "+f"(c[0]), "+f"(c[1]), "+f"(c[2]), "+f"(c[3])
        : "r"(a[0]), "r"(a[1]), "r"(a[2]), "r"(a[3]), "r"(b[0]), "r"(b[1]));
}

// ---------------------------------------------------------------------------
// fp16 mma.sync GEMM: C[128,128] = A[128,1024] * W[128,1024]^T + bias
// (unchanged from round 10)
// ---------------------------------------------------------------------------
#define MM_SMEM_BYTES 32768

template <bool SCATTER>
__device__ __forceinline__ void mm_core(const float* __restrict__ A,
                                        const float* __restrict__ W,
                                        const float* __restrict__ bias,
                                        float* __restrict__ out,
                                        int m0, int n0) {
    extern __shared__ char smem[];
    const int tid = threadIdx.x;
    const int lane = tid & 31;
    const int wid = tid >> 5;
    const int warp_m = wid & 1;
    const int warp_n = wid >> 1;

    float c[4][4][4];
#pragma unroll
    for (int i = 0; i < 4; i++)
#pragma unroll
        for (int j = 0; j < 4; j++)
#pragma unroll
            for (int e = 0; e < 4; e++) c[i][j][e] = 0.0f;

    const float* Abase = A + (size_t)m0 * DD;
    const float* Wbase = W + (size_t)n0 * DD;

    float4 av[4], bv[4];

#define STORE_STAGE(bufp)                                                     \
    do {                                                                      \
        char* sbA = smem + (bufp) * 16384;                                    \
        char* sbB = sbA + 8192;                                               \
        _Pragma("unroll") for (int i = 0; i < 4; i++) {                       \
            const int idx = tid + i * 256;                                    \
            const int row = idx >> 3, k4 = idx & 7;                           \
            const int kt = k4 >> 2;                                           \
            const int p0 = (k4 & 3) * 2;                                      \
            const uint32_t w0 = pack_f16x2(av[i].x, av[i].y);                 \
            const uint32_t w1 = pack_f16x2(av[i].z, av[i].w);                 \
            const uint32_t u0 = pack_f16x2(bv[i].x, bv[i].y);                 \
            const uint32_t u1 = pack_f16x2(bv[i].z, bv[i].w);                 \
            { /* A pack */                                                    \
                const int rm = row & 15, mt = row >> 4;                       \
                const int aidx = (rm >> 3) + ((p0 >> 2) << 1);                \
                const int slotA = kt * 8 + mt;                                \
                const int lb = (rm & 7) * 4 + (p0 & 3);                       \
                *(uint32_t*)(sbA + ((slotA * 32 + (lb ^ kt)) << 4)            \
                             + (aidx << 2)) = w0;                             \
                *(uint32_t*)(sbA + ((slotA * 32 + ((lb + 1) ^ kt)) << 4)      \
                             + (aidx << 2)) = w1;                             \
            }                                                                 \
            { /* B pack */                                                    \
                const int rn = row & 7, nt = row >> 3;                        \
                const int bidx = p0 >> 2;                                     \
                const int slotB = kt * 16 + nt;                               \
                const int lb = rn * 4 + (p0 & 3);                             \
                *(uint32_t*)(sbB + ((slotB * 32 + (lb ^ kt)) << 3)            \
                             + (bidx << 2)) = u0;                             \
                *(uint32_t*)(sbB + ((slotB * 32 + ((lb + 1) ^ kt)) << 3)      \
                             + (bidx << 2)) = u1;                             \
            }                                                                 \
        }                                                                     \
    } while (0)

#define LOAD_STAGE(c0)                                                        \
    do {                                                                      \
        _Pragma("unroll") for (int i = 0; i < 4; i++) {                       \
            const int idx = tid + i * 256;                                    \
            const int row = idx >> 3, k4 = idx & 7;                           \
            av[i] = *(const float4*)(Abase + (size_t)row * DD + (c0) + k4 * 4); \
            bv[i] = *(const float4*)(Wbase + (size_t)row * DD + (c0) + k4 * 4); \
        }                                                                     \
    } while (0)

    LOAD_STAGE(0);

    for (int ch = 0; ch < 32; ++ch) {
        const int buf = ch & 1;
        STORE_STAGE(buf);
        if (ch + 1 < 32) LOAD_STAGE((ch + 1) * 32);
        __syncthreads();

        const char* sbA = smem + buf * 16384;
        const char* sbB = sbA + 8192;
#pragma unroll
        for (int kt = 0; kt < 2; ++kt) {
            uint32_t af[4][4];
            uint32_t bf[4][2];
#pragma unroll
            for (int i = 0; i < 4; ++i) {
                const uint4 v = *(const uint4*)(sbA +
                    (((kt * 8 + warp_m * 4 + i) * 32 + (lane ^ kt)) << 4));
                af[i][0] = v.x; af[i][1] = v.y;
                af[i][2] = v.z; af[i][3] = v.w;
            }
#pragma unroll
            for (int j = 0; j < 4; ++j) {
                const uint2 v = *(const uint2*)(sbB +
                    (((kt * 16 + warp_n * 4 + j) * 32 + (lane ^ kt)) << 3));
                bf[j][0] = v.x; bf[j][1] = v.y;
            }
#pragma unroll
            for (int i = 0; i < 4; ++i)
#pragma unroll
                for (int j = 0; j < 4; ++j) mma_fp16(c[i][j], af[i], bf[j]);
        }
    }

#pragma unroll
    for (int i = 0; i < 4; ++i) {
        const int r0 = m0 + warp_m * 64 + i * 16 + (lane >> 2);
#pragma unroll
        for (int j = 0; j < 4; ++j) {
            const int cb = n0 + warp_n * 32 + j * 8 + 2 * (lane & 3);
            const float b0 = bias[cb], b1 = bias[cb + 1];
            float2 lo = {c[i][j][0] + b0, c[i][j][1] + b1};
            float2 hi = {c[i][j][2] + b0, c[i][j][3] + b1};
            if (SCATTER) {
                const int h = cb >> 6, d = cb & 63;
                const int bA = r0 >> 11, s0 = r0 & 2047;
                float* p0 = out + (((size_t)(bA * HH + h)) * SS + s0) * DK + d;
                *(float2*)p0 = lo;
                const int r1 = r0 + 8;
                const int bB = r1 >> 11, s1 = r1 & 2047;
                float* p1 = out + (((size_t)(bB * HH + h)) * SS + s1) * DK + d;
                *(float2*)p1 = hi;
            } else {
                *(float2*)(out + (size_t)r0 * DD + cb) = lo;
                *(float2*)(out + (size_t)(r0 + 8) * DD + cb) = hi;
            }
        }
    }
#undef STORE_STAGE
#undef LOAD_STAGE
}

__global__ void __launch_bounds__(256) qkv_mm_kernel(
    const float* __restrict__ x,
    const float* __restrict__ Wq, const float* __restrict__ bq,
    const float* __restrict__ Wk, const float* __restrict__ bk,
    const float* __restrict__ Wv, const float* __restrict__ bv) {
    const int z = blockIdx.z;
    const float* W = (z == 0) ? Wq : (z == 1) ? Wk : Wv;
    const float* bias = (z == 0) ? bq : (z == 1) ? bk : bv;
    float* out = (z == 0) ? g_q : (z == 1) ? g_k : g_v;
    mm_core<true>(x, W, bias, out, blockIdx.y * 128, blockIdx.x * 128);
}

__global__ void __launch_bounds__(256) oproj_mm_kernel(
    const float* __restrict__ Wo, const float* __restrict__ bo,
    float* __restrict__ out) {
    mm_core<false>(g_ctx, Wo, bo, out, blockIdx.y * 128, blockIdx.x * 128);
}

// ---------------------------------------------------------------------------
// Tensor-core flash attention, round 11:
//  - QK bf16 3-term m16n8k16 (unchanged)
//  - PV fp16 m16n8k16 with P ENTIRELY IN REGISTERS: the QK C-fragment IS the
//    PV A-fragment for k16 (FA2 trick) -> no P smem, PV mmas halved.
//  - V stored as f16x2 key-pairs matching the fp16 B-fragment; V smem/LDS/STS
//    halved. Log2-domain softmax.
//
// smem map (bytes):
//   buf b (b=0,1) at b*24576:
//     K : 32 slots x 32 lanes x 16B = 16384 {kh_b0,kh_b1,kl_b0,kl_b1} bf16x2
//     V : at +16384, 32 slots (kk*8+j) x 32 lanes x 8B = 8192 (f16x2 keypairs)
//   mask: 49152 + b*256 (64 floats each)
// ---------------------------------------------------------------------------
#define ATTN_SMEM 49664
#define A_BUFSTRIDE 24576
#define A_VOFF 16384
#define A_MSK 49152
#define QSCALE (0.125f * 1.44269504088896f)   // (1/sqrt(DK)) * log2(e)

__global__ void __launch_bounds__(256, 1) attn_kernel(const int* __restrict__ mask) {
    extern __shared__ char smem[];
    const int tid = threadIdx.x;
    const int lane = tid & 31;
    const int w = tid >> 5;
    const int gid = lane >> 2;
    const int tig = lane & 3;

    const int bh = blockIdx.y;
    const int b = bh >> 4;
    const int h = bh & 15;
    const int qs_base = blockIdx.x * 128 + w * 16;

    const float* qbase = g_q + (size_t)bh * SS * DK;
    const float* kbase = g_k + (size_t)bh * SS * DK;
    const float* vbase = g_v + (size_t)bh * SS * DK;

    // ---- Q fragments: bf16 hi/lo, m16n8k16 A layout, scale*log2e folded ----
    uint32_t qh[4][4], ql[4][4];
#pragma unroll
    for (int kt = 0; kt < 4; ++kt) {
#pragma unroll
        for (int r = 0; r < 4; ++r) {
            const int row = qs_base + gid + (r & 1) * 8;
            const int d = kt * 16 + 2 * tig + (r >> 1) * 8;
            const float2 qv = *(const float2*)(qbase + (size_t)row * DK + d);
            const float f0 = qv.x * QSCALE, f1 = qv.y * QSCALE;
            const uint32_t hw = pack_bf16x2(f0, f1);
            qh[kt][r] = hw;
            ql[kt][r] = pack_bf16x2(f0 - bf16lo_f(hw), f1 - bf16hi_f(hw));
        }
    }

    float o[8][4];
#pragma unroll
    for (int j = 0; j < 8; ++j)
#pragma unroll
        for (int e = 0; e < 4; ++e) o[j][e] = 0.0f;
    float m0 = -1e30f, m1 = -1e30f, l0 = 0.0f, l1 = 0.0f;

    // staging registers (pipelined): tile t data loaded during tile t-1.
    // K: 4 x float4 (row = idx>>4, p4 = idx&15)
    // V: 4 units (kp = idx>>5 keypair, dp = idx&31), 2 x float2 each
    float4 rk[4];
    float2 rv0[4], rv1[4];
    int rmask = 1;

    // prologue: LDG tile 0
#pragma unroll
    for (int i = 0; i < 4; ++i) {
        const int idx = tid + i * 256;
        const int row = idx >> 4, p4 = idx & 15;
        rk[i] = *(const float4*)(kbase + (size_t)row * DK + p4 * 4);
    }
#pragma unroll
    for (int u = 0; u < 4; ++u) {
        const int idx = tid + u * 256;
        const int kp = idx >> 5, dp = idx & 31;
        rv0[u] = *(const float2*)(vbase + (size_t)(2 * kp) * DK + 2 * dp);
        rv1[u] = *(const float2*)(vbase + (size_t)(2 * kp + 1) * DK + 2 * dp);
    }
    if (tid < 64) rmask = mask[b * SS + tid];

    for (int t = 0; t < SS / 64; ++t) {
        const int buf = t & 1;
        char* kb = smem + buf * A_BUFSTRIDE;
        char* vb = kb + A_VOFF;

        // ---- STS staged tile t ----
#pragma unroll
        for (int i = 0; i < 4; ++i) {
            const int idx = tid + i * 256;
            const int row = idx >> 4, p4 = idx & 15;
            const float ke[4] = {rk[i].x, rk[i].y, rk[i].z, rk[i].w};
            // K: bf16 hi/lo pairs
#pragma unroll
            for (int ep = 0; ep < 2; ++ep) {
                const int d0 = p4 * 4 + ep * 2;
                const int kt = d0 >> 4, dd = d0 & 15;
                const int reg = dd >> 3, quad = (dd >> 1) & 3;
                const int laneK = (((row & 7) * 4 + quad) ^ kt);
                char* base = kb + (((kt * 8 + (row >> 3)) * 32 + laneK) << 4)
                             + (reg << 2);
                const float f0 = ke[ep * 2], f1 = ke[ep * 2 + 1];
                const uint32_t hw = pack_bf16x2(f0, f1);
                *(uint32_t*)(base) = hw;
                *(uint32_t*)(base + 8) =
                    pack_bf16x2(f0 - bf16lo_f(hw), f1 - bf16hi_f(hw));
            }
        }
        // V: f16x2 key-pairs in B-fragment layout
#pragma unroll
        for (int u = 0; u < 4; ++u) {
            const int idx = tid + u * 256;
            const int kp = idx >> 5, dp = idx & 31;
            const int kk = kp >> 3, kpb = kp & 7;
            const int word = kpb >> 2, tigv = kpb & 3;
            const uint32_t w0 = pack_f16x2(rv0[u].x, rv1[u].x);
            const uint32_t w1 = pack_f16x2(rv0[u].y, rv1[u].y);
#pragma unroll
            for (int e = 0; e < 2; ++e) {
                const int d = 2 * dp + e;
                const int j = d >> 3, gidv = d & 7;
                const int lane_s = (4 * gidv + tigv) ^ j;
                *(uint32_t*)(vb + (((kk * 8 + j) * 32 + lane_s) << 3) +
                             (word << 2)) = (e == 0) ? w0 : w1;
            }
        }
        if (tid < 64)
            *(float*)(smem + A_MSK + buf * 256 + tid * 4) = rmask ? 0.0f : -1e9f;

        // ---- LDG tile t+1 (latency hidden under compute of tile t) ----
        if (t + 1 < SS / 64) {
            const int key0n = (t + 1) * 64;
#pragma unroll
            for (int i = 0; i < 4; ++i) {
                const int idx = tid + i * 256;
                const int row = idx >> 4, p4 = idx & 15;
                rk[i] = *(const float4*)(kbase + (size_t)(key0n + row) * DK + p4 * 4);
            }
#pragma unroll
            for (int u = 0; u < 4; ++u) {
                const int idx = tid + u * 256;
                const int kp = idx >> 5, dp = idx & 31;
                rv0[u] = *(const float2*)(vbase +
                    (size_t)(key0n + 2 * kp) * DK + 2 * dp);
                rv1[u] = *(const float2*)(vbase +
                    (size_t)(key0n + 2 * kp + 1) * DK + 2 * dp);
            }
            if (tid < 64) rmask = mask[b * SS + key0n + tid];
        }
        __syncthreads();

        // ---- scores (log2-domain): S = Q K^T via bf16 3-term ----
        float sc[8][4];
#pragma unroll
        for (int j = 0; j < 8; ++j)
#pragma unroll
            for (int e = 0; e < 4; ++e) sc[j][e] = 0.0f;
#pragma unroll
        for (int kt = 0; kt < 4; ++kt) {
#pragma unroll
            for (int j = 0; j < 8; ++j) {
                const uint4 k4v = *(const uint4*)(kb + (((kt * 8 + j) << 9) +
                                                       ((lane ^ kt) << 4)));
                uint32_t kh2[2] = {k4v.x, k4v.y};
                uint32_t kl2[2] = {k4v.z, k4v.w};
                mma_bf16(sc[j], qh[kt], kh2);
                mma_bf16(sc[j], qh[kt], kl2);
                mma_bf16(sc[j], ql[kt], kh2);
            }
        }

        // ---- mask, online softmax (log2-domain); overwrite sc with P ----
        const char* mbuf = smem + A_MSK + buf * 256;
#pragma unroll
        for (int j = 0; j < 8; ++j) {
            const float2 ma = *(const float2*)(mbuf + (j * 8 + 2 * tig) * 4);
            sc[j][0] += ma.x; sc[j][1] += ma.y;
            sc[j][2] += ma.x; sc[j][3] += ma.y;
        }
        float rm0 = -1e30f, rm1 = -1e30f;
#pragma unroll
        for (int j = 0; j < 8; ++j) {
            rm0 = fmaxf(rm0, fmaxf(sc[j][0], sc[j][1]));
            rm1 = fmaxf(rm1, fmaxf(sc[j][2], sc[j][3]));
        }
        rm0 = fmaxf(rm0, __shfl_xor_sync(0xFFFFFFFF, rm0, 1));
        rm0 = fmaxf(rm0, __shfl_xor_sync(0xFFFFFFFF, rm0, 2));
        rm1 = fmaxf(rm1, __shfl_xor_sync(0xFFFFFFFF, rm1, 1));
        rm1 = fmaxf(rm1, __shfl_xor_sync(0xFFFFFFFF, rm1, 2));
        const float nm0 = fmaxf(m0, rm0), nm1 = fmaxf(m1, rm1);
        const float c0 = ex2(m0 - nm0), c1 = ex2(m1 - nm1);
        m0 = nm0; m1 = nm1;
        l0 *= c0; l1 *= c1;
#pragma unroll
        for (int j = 0; j < 8; ++j) {
            o[j][0] *= c0; o[j][1] *= c0;
            o[j][2] *= c1; o[j][3] *= c1;
        }
        float s0 = 0.0f, s1 = 0.0f;
#pragma unroll
        for (int j = 0; j < 8; ++j) {
            const float p0 = ex2(sc[j][0] - nm0);
            const float p1 = ex2(sc[j][1] - nm0);
            const float p2 = ex2(sc[j][2] - nm1);
            const float p3 = ex2(sc[j][3] - nm1);
            s0 += p0 + p1; s1 += p2 + p3;
            sc[j][0] = p0; sc[j][1] = p1; sc[j][2] = p2; sc[j][3] = p3;
        }
        l0 += s0; l1 += s1;

        // ---- O += P V (fp16 k16; P direct from registers) ----
#pragma unroll
        for (int kk = 0; kk < 4; ++kk) {
            uint32_t pa[4];
            pa[0] = pack_f16x2(sc[2 * kk][0], sc[2 * kk][1]);
            pa[1] = pack_f16x2(sc[2 * kk][2], sc[2 * kk][3]);
            pa[2] = pack_f16x2(sc[2 * kk + 1][0], sc[2 * kk + 1][1]);
            pa[3] = pack_f16x2(sc[2 * kk + 1][2], sc[2 * kk + 1][3]);
#pragma unroll
            for (int j = 0; j < 8; ++j) {
                uint32_t bvf[2];
                const uint2 bv2 = *(const uint2*)(vb +
                    (((kk * 8 + j) * 32 + (lane ^ j)) << 3));
                bvf[0] = bv2.x; bvf[1] = bv2.y;
                mma_fp16(o[j], pa, bvf);
            }
        }
    }

    // ---- finalize ----
    float lt0 = l0, lt1 = l1;
    lt0 += __shfl_xor_sync(0xFFFFFFFF, lt0, 1);
    lt0 += __shfl_xor_sync(0xFFFFFFFF, lt0, 2);
    lt1 += __shfl_xor_sync(0xFFFFFFFF, lt1, 1);
    lt1 += __shfl_xor_sync(0xFFFFFFFF, lt1, 2);
    const float inv0 = 1.0f / lt0, inv1 = 1.0f / lt1;

    const int r0 = qs_base + gid, r1 = r0 + 8;
    float* o0 = g_ctx + ((size_t)(b * SS + r0)) * DD + h * DK;
    float* o1 = g_ctx + ((size_t)(b * SS + r1)) * DD + h * DK;
#pragma unroll
    for (int j = 0; j < 8; ++j) {
        const int cb = j * 8 + 2 * tig;
        float2 v0 = {o[j][0] * inv0, o[j][1] * inv0};
        float2 v1 = {o[j][2] * inv1, o[j][3] * inv1};
        *(float2*)(o0 + cb) = v0;
        *(float2*)(o1 + cb) = v1;
    }
}

// ---------------------------------------------------------------------------
// Inputs (metadata order): x, mask, Wq, bq, Wk, bk, Wv, bv, Wo, bo
// ---------------------------------------------------------------------------
extern "C" void kernel_launch(void* const* d_in, const int* in_sizes, int n_in,
                              void* d_out, int out_size) {
    const float* x  = (const float*)d_in[0];
    const int*   mk = (const int*)d_in[1];
    const float* Wq = (const float*)d_in[2];
    const float* bq = (const float*)d_in[3];
    const float* Wk = (const float*)d_in[4];
    const float* bk = (const float*)d_in[5];
    const float* Wv = (const float*)d_in[6];
    const float* bv = (const float*)d_in[7];
    const float* Wo = (const float*)d_in[8];
    const float* bo = (const float*)d_in[9];
    float* out = (float*)d_out;

    static bool configured = false;
    if (!configured) {
        cudaFuncSetAttribute(qkv_mm_kernel,
                             cudaFuncAttributeMaxDynamicSharedMemorySize,
                             MM_SMEM_BYTES);
        cudaFuncSetAttribute(oproj_mm_kernel,
                             cudaFuncAttributeMaxDynamicSharedMemorySize,
                             MM_SMEM_BYTES);
        cudaFuncSetAttribute(attn_kernel,
                             cudaFuncAttributeMaxDynamicSharedMemorySize,
                             ATTN_SMEM);
        configured = true;
    }

    // QKV projections (fp16 mma.sync, fp32 accumulate), scattered to (B,H,S,DK)
    qkv_mm_kernel<<<dim3(DD / 128, MM / 128, 3), 256, MM_SMEM_BYTES>>>(
        x, Wq, bq, Wk, bk, Wv, bv);

    // Tensor-core flash attention (bf16 QK, fp16 PV register-direct)
    attn_kernel<<<dim3(SS / 128, BB * HH), 256, ATTN_SMEM>>>(mk);

    // Output projection (fp16 mma.sync) -> d_out
    oproj_mm_kernel<<<dim3(DD / 128, MM / 128), 256, MM_SMEM_BYTES>>>(Wo, bo, out);
}

// round 13
// speedup vs baseline: 1.7841x; 1.0993x over previous
#include <cuda_runtime.h>
#include <cstdint>

// Problem constants (fixed by the dataset)
#define BB 2
#define SS 2048
#define DD 1024
#define HH 16
#define DK 64
#define MM (BB * SS)  // 4096 rows

// Scratch (allocation-free rule: __device__ globals)
__device__ float g_q[(size_t)BB * HH * SS * DK];    // (B,H,S,DK) fp32
__device__ float g_ctx[(size_t)BB * SS * DD];       // (B,S,D)
// K packed: per (bh, tile): 32 slots x 32 lanes x 16B {kh0,kh1,kl0,kl1} = 16KB
__device__ char g_kp[(size_t)BB * HH * 32 * 16384];
// V packed: per (bh, tile): 32 slots x 32 lanes x 8B {w0,w1} f16x2 = 8KB
__device__ char g_vp[(size_t)BB * HH * 32 * 8192];

// ---------------------------------------------------------------------------
// helpers (baseline sm_80+ ISA — no 'a'-suffix features)
// ---------------------------------------------------------------------------
__device__ __forceinline__ float ex2(float x) {
    float r;
    asm("ex2.approx.ftz.f32 %0, %1;" : "=f"(r) : "f"(x));
    return r;
}
__device__ __forceinline__ uint32_t pack_bf16x2(float lo, float hi) {
    uint32_t r;
    asm("cvt.rn.bf16x2.f32 %0, %1, %2;" : "=r"(r) : "f"(hi), "f"(lo));
    return r;
}
__device__ __forceinline__ uint32_t pack_f16x2(float lo, float hi) {
    uint32_t r;
    asm("cvt.rn.f16x2.f32 %0, %1, %2;" : "=r"(r) : "f"(hi), "f"(lo));
    return r;
}
__device__ __forceinline__ float bf16lo_f(uint32_t w) {
    return __uint_as_float(w << 16);
}
__device__ __forceinline__ float bf16hi_f(uint32_t w) {
    return __uint_as_float(w & 0xFFFF0000u);
}
__device__ __forceinline__ uint32_t smem_u32(const void* p) {
    uint32_t a;
    asm("{ .reg .u64 t; cvta.to.shared.u64 t, %1; cvt.u32.u64 %0, t; }"
        : "=r"(a) : "l"(p));
    return a;
}
__device__ __forceinline__ void cp16(uint32_t s, const void* g) {
    asm volatile("cp.async.cg.shared.global [%0], [%1], 16;"
                 :: "r"(s), "l"(g) : "memory");
}
#define CP_COMMIT() asm volatile("cp.async.commit_group;" ::: "memory")
#define CP_WAIT0()  asm volatile("cp.async.wait_group 0;" ::: "memory")

__device__ __forceinline__ void mma_bf16(float c[4], const uint32_t a[4],
                                         const uint32_t b[2]) {
    asm volatile(
        "mma.sync.aligned.m16n8k16.row.col.f32.bf16.bf16.f32 "
        "{%0,%1,%2,%3}, {%4,%5,%6,%7}, {%8,%9}, {%0,%1,%2,%3};"
        : "+f"(c[0]), "+f"(c[1]), "+f"(c[2]), "+f"(c[3])
        : "r"(a[0]), "r"(a[1]), "r"(a[2]), "r"(a[3]), "r"(b[0]), "r"(b[1]));
}
__device__ __forceinline__ void mma_fp16(float c[4], const uint32_t a[4],
                                         const uint32_t b[2]) {
    asm volatile(
        "mma.sync.aligned.m16n8k16.row.col.f32.f16.f16.f32 "
        "{%0,%1,%2,%3}, {%4,%5,%6,%7}, {%8,%9}, {%0,%1,%2,%3};"
        : "+f"(c[0]), "+f"(c[1]), "+f"(c[2]), "+f"(c[3])
        : "r"(a[0]), "r"(a[1]), "r"(a[2]), "r"(a[3]), "r"(b[0]), "r"(b[1]));
}

// ---------------------------------------------------------------------------
// K/V producer-side packing (formulas cloned from the R11 attn STS code)
// ---------------------------------------------------------------------------
__device__ __forceinline__ void store_k_pair(int m, int cb, float f0, float f1) {
    const int b_ = m >> 11, s = m & 2047, h = cb >> 6, d = cb & 63;
    const int t = s >> 6, rw = s & 63;
    const int kt = d >> 4, dd = d & 15, quad = (dd >> 1) & 3, reg = dd >> 3;
    const int laneK = (((rw & 7) * 4) + quad) ^ kt;
    char* base = g_kp + ((size_t)((b_ * HH + h) * 32 + t) << 14) +
                 (((kt * 8 + (rw >> 3)) * 32 + laneK) << 4) + (reg << 2);
    const uint32_t kh = pack_bf16x2(f0, f1);
    const uint32_t kl = pack_bf16x2(f0 - bf16lo_f(kh), f1 - bf16hi_f(kh));
    *(uint32_t*)base = kh;
    *(uint32_t*)(base + 8) = kl;
}

// m = even row; values f* for row m, g* for row m+1, at cols (cb, cb+1)
__device__ __forceinline__ void store_v_pair(int m, int cb, float f0, float f1,
                                             float g0, float g1) {
    const int b_ = m >> 11, s = m & 2047, h = cb >> 6, d = cb & 63;
    const int t = s >> 6, kp = (s & 63) >> 1;
    const int kk = kp >> 3, kpb = kp & 7, word = kpb >> 2, tigv = kpb & 3;
    const int jv = d >> 3, gv = d & 7;
    char* tile = g_vp + ((size_t)((b_ * HH + h) * 32 + t) << 13);
    const uint32_t w0 = pack_f16x2(f0, g0);
    const uint32_t w1 = pack_f16x2(f1, g1);
    const int l0 = (4 * gv + tigv) ^ jv;
    const int l1 = (4 * (gv + 1) + tigv) ^ jv;
    *(uint32_t*)(tile + (((kk * 8 + jv) * 32 + l0) << 3) + (word << 2)) = w0;
    *(uint32_t*)(tile + (((kk * 8 + jv) * 32 + l1) << 3) + (word << 2)) = w1;
}

// ---------------------------------------------------------------------------
// fp16 mma.sync GEMM: C[128,128] = A[128,1024] * W[128,1024]^T + bias
// MODE: 0 = plain row-major out, 1 = Q scatter fp32, 2 = K pack, 3 = V pack
// ---------------------------------------------------------------------------
#define MM_SMEM_BYTES 32768

template <int MODE>
__device__ __forceinline__ void mm_core(const float* __restrict__ A,
                                        const float* __restrict__ W,
                                        const float* __restrict__ bias,
                                        float* __restrict__ out,
                                        int m0, int n0) {
    extern __shared__ char smem[];
    const int tid = threadIdx.x;
    const int lane = tid & 31;
    const int wid = tid >> 5;
    const int warp_m = wid & 1;
    const int warp_n = wid >> 1;

    float c[4][4][4];
#pragma unroll
    for (int i = 0; i < 4; i++)
#pragma unroll
        for (int j = 0; j < 4; j++)
#pragma unroll
            for (int e = 0; e < 4; e++) c[i][j][e] = 0.0f;

    const float* Abase = A + (size_t)m0 * DD;
    const float* Wbase = W + (size_t)n0 * DD;

    float4 av[4], bv[4];

#define STORE_STAGE(bufp)                                                     \
    do {                                                                      \
        char* sbA = smem + (bufp) * 16384;                                    \
        char* sbB = sbA + 8192;                                               \
        _Pragma("unroll") for (int i = 0; i < 4; i++) {                       \
            const int idx = tid + i * 256;                                    \
            const int row = idx >> 3, k4 = idx & 7;                           \
            const int kt = k4 >> 2;                                           \
            const int p0 = (k4 & 3) * 2;                                      \
            const uint32_t w0 = pack_f16x2(av[i].x, av[i].y);                 \
            const uint32_t w1 = pack_f16x2(av[i].z, av[i].w);                 \
            const uint32_t u0 = pack_f16x2(bv[i].x, bv[i].y);                 \
            const uint32_t u1 = pack_f16x2(bv[i].z, bv[i].w);                 \
            { /* A pack */                                                    \
                const int rm = row & 15, mt = row >> 4;                       \
                const int aidx = (rm >> 3) + ((p0 >> 2) << 1);                \
                const int slotA = kt * 8 + mt;                                \
                const int lb = (rm & 7) * 4 + (p0 & 3);                       \
                *(uint32_t*)(sbA + ((slotA * 32 + (lb ^ kt)) << 4)            \
                             + (aidx << 2)) = w0;                             \
                *(uint32_t*)(sbA + ((slotA * 32 + ((lb + 1) ^ kt)) << 4)      \
                             + (aidx << 2)) = w1;                             \
            }                                                                 \
            { /* B pack */                                                    \
                const int rn = row & 7, nt = row >> 3;                        \
                const int bidx = p0 >> 2;                                     \
                const int slotB = kt * 16 + nt;                               \
                const int lb = rn * 4 + (p0 & 3);                             \
                *(uint32_t*)(sbB + ((slotB * 32 + (lb ^ kt)) << 3)            \
                             + (bidx << 2)) = u0;                             \
                *(uint32_t*)(sbB + ((slotB * 32 + ((lb + 1) ^ kt)) << 3)      \
                             + (bidx << 2)) = u1;                             \
            }                                                                 \
        }                                                                     \
    } while (0)

#define LOAD_STAGE(c0)                                                        \
    do {                                                                      \
        _Pragma("unroll") for (int i = 0; i < 4; i++) {                       \
            const int idx = tid + i * 256;                                    \
            const int row = idx >> 3, k4 = idx & 7;                           \
            av[i] = *(const float4*)(Abase + (size_t)row * DD + (c0) + k4 * 4); \
            bv[i] = *(const float4*)(Wbase + (size_t)row * DD + (c0) + k4 * 4); \
        }                                                                     \
    } while (0)

    LOAD_STAGE(0);

    for (int ch = 0; ch < 32; ++ch) {
        const int buf = ch & 1;
        STORE_STAGE(buf);
        if (ch + 1 < 32) LOAD_STAGE((ch + 1) * 32);
        __syncthreads();

        const char* sbA = smem + buf * 16384;
        const char* sbB = sbA + 8192;
#pragma unroll
        for (int kt = 0; kt < 2; ++kt) {
            uint32_t af[4][4];
            uint32_t bf[4][2];
#pragma unroll
            for (int i = 0; i < 4; ++i) {
                const uint4 v = *(const uint4*)(sbA +
                    (((kt * 8 + warp_m * 4 + i) * 32 + (lane ^ kt)) << 4));
                af[i][0] = v.x; af[i][1] = v.y;
                af[i][2] = v.z; af[i][3] = v.w;
            }
#pragma unroll
            for (int j = 0; j < 4; ++j) {
                const uint2 v = *(const uint2*)(sbB +
                    (((kt * 16 + warp_n * 4 + j) * 32 + (lane ^ kt)) << 3));
                bf[j][0] = v.x; bf[j][1] = v.y;
            }
#pragma unroll
            for (int i = 0; i < 4; ++i)
#pragma unroll
                for (int j = 0; j < 4; ++j) mma_fp16(c[i][j], af[i], bf[j]);
        }
    }

#pragma unroll
    for (int i = 0; i < 4; ++i) {
        const int r0 = m0 + warp_m * 64 + i * 16 + (lane >> 2);
#pragma unroll
        for (int j = 0; j < 4; ++j) {
            const int cb = n0 + warp_n * 32 + j * 8 + 2 * (lane & 3);
            const float b0 = bias[cb], b1 = bias[cb + 1];
            float2 lo = {c[i][j][0] + b0, c[i][j][1] + b1};
            float2 hi = {c[i][j][2] + b0, c[i][j][3] + b1};
            if (MODE == 0) {
                *(float2*)(out + (size_t)r0 * DD + cb) = lo;
                *(float2*)(out + (size_t)(r0 + 8) * DD + cb) = hi;
            } else if (MODE == 1) {
                const int h = cb >> 6, d = cb & 63;
                const int bA = r0 >> 11, s0 = r0 & 2047;
                float* p0 = out + (((size_t)(bA * HH + h)) * SS + s0) * DK + d;
                *(float2*)p0 = lo;
                const int r1 = r0 + 8;
                const int bB = r1 >> 11, s1 = r1 & 2047;
                float* p1 = out + (((size_t)(bB * HH + h)) * SS + s1) * DK + d;
                *(float2*)p1 = hi;
            } else if (MODE == 2) {
                store_k_pair(r0, cb, lo.x, lo.y);
                store_k_pair(r0 + 8, cb, hi.x, hi.y);
            } else {
                // V: pair rows (r, r+1); partner row values live at lane+4
                const float p0x = __shfl_down_sync(0xFFFFFFFF, lo.x, 4);
                const float p0y = __shfl_down_sync(0xFFFFFFFF, lo.y, 4);
                const float p1x = __shfl_down_sync(0xFFFFFFFF, hi.x, 4);
                const float p1y = __shfl_down_sync(0xFFFFFFFF, hi.y, 4);
                if (((lane >> 2) & 1) == 0) {
                    store_v_pair(r0, cb, lo.x, lo.y, p0x, p0y);
                    store_v_pair(r0 + 8, cb, hi.x, hi.y, p1x, p1y);
                }
            }
        }
    }
#undef STORE_STAGE
#undef LOAD_STAGE
}

__global__ void __launch_bounds__(256) qkv_mm_kernel(
    const float* __restrict__ x,
    const float* __restrict__ Wq, const float* __restrict__ bq,
    const float* __restrict__ Wk, const float* __restrict__ bk,
    const float* __restrict__ Wv, const float* __restrict__ bv) {
    const int z = blockIdx.z;
    const int m0 = blockIdx.y * 128, n0 = blockIdx.x * 128;
    if (z == 0)
        mm_core<1>(x, Wq, bq, g_q, m0, n0);
    else if (z == 1)
        mm_core<2>(x, Wk, bk, nullptr, m0, n0);
    else
        mm_core<3>(x, Wv, bv, nullptr, m0, n0);
}

__global__ void __launch_bounds__(256) oproj_mm_kernel(
    const float* __restrict__ Wo, const float* __restrict__ bo,
    float* __restrict__ out) {
    mm_core<0>(g_ctx, Wo, bo, out, blockIdx.y * 128, blockIdx.x * 128);
}

// ---------------------------------------------------------------------------
// Tensor-core flash attention, round 12:
//  - K/V arrive PRE-PACKED from the projection kernel; staging is a pure
//    cp.async linear copy (no regs, no cvt, no STS) -> 2 CTAs/SM.
//  - QK bf16 3-term m16n8k16; PV fp16 k16 register-direct; log2 softmax.
//
// smem map (bytes): buf b at b*24576 {K 16KB, V 8KB}; mask at 49152+b*256
// ---------------------------------------------------------------------------
#define ATTN_SMEM 49664
#define A_BUFSTRIDE 24576
#define A_VOFF 16384
#define A_MSK 49152
#define QSCALE (0.125f * 1.44269504088896f)   // (1/sqrt(DK)) * log2(e)

__global__ void __launch_bounds__(256, 2) attn_kernel(const int* __restrict__ mask) {
    extern __shared__ char smem[];
    const uint32_t sb = smem_u32(smem);
    const int tid = threadIdx.x;
    const int lane = tid & 31;
    const int w = tid >> 5;
    const int gid = lane >> 2;
    const int tig = lane & 3;

    const int bh = blockIdx.y;
    const int b = bh >> 4;
    const int h = bh & 15;
    const int qs_base = blockIdx.x * 128 + w * 16;

    const float* qbase = g_q + (size_t)bh * SS * DK;
    const char* gkb = g_kp + ((size_t)bh << 19);
    const char* gvb = g_vp + ((size_t)bh << 18);

    // ---- Q fragments: bf16 hi/lo, m16n8k16 A layout, scale*log2e folded ----
    uint32_t qh[4][4], ql[4][4];
#pragma unroll
    for (int kt = 0; kt < 4; ++kt) {
#pragma unroll
        for (int r = 0; r < 4; ++r) {
            const int row = qs_base + gid + (r & 1) * 8;
            const int d = kt * 16 + 2 * tig + (r >> 1) * 8;
            const float2 qv = *(const float2*)(qbase + (size_t)row * DK + d);
            const float f0 = qv.x * QSCALE, f1 = qv.y * QSCALE;
            const uint32_t hw = pack_bf16x2(f0, f1);
            qh[kt][r] = hw;
            ql[kt][r] = pack_bf16x2(f0 - bf16lo_f(hw), f1 - bf16hi_f(hw));
        }
    }

    float o[8][4];
#pragma unroll
    for (int j = 0; j < 8; ++j)
#pragma unroll
        for (int e = 0; e < 4; ++e) o[j][e] = 0.0f;
    float m0 = -1e30f, m1 = -1e30f, l0 = 0.0f, l1 = 0.0f;

    // prologue: async-copy tile 0 into buf 0; prefetch mask
    {
        const uint32_t kd = sb;
        const char* gk = gkb;
#pragma unroll
        for (int i = 0; i < 4; ++i)
            cp16(kd + (tid + i * 256) * 16, gk + (size_t)(tid + i * 256) * 16);
        const uint32_t vd = sb + A_VOFF;
        const char* gv = gvb;
#pragma unroll
        for (int i = 0; i < 2; ++i)
            cp16(vd + (tid + i * 256) * 16, gv + (size_t)(tid + i * 256) * 16);
        CP_COMMIT();
    }
    int rmask = 1;
    if (tid < 64) rmask = mask[b * SS + tid];

    for (int t = 0; t < SS / 64; ++t) {
        const int buf = t & 1;
        const char* kb = smem + buf * A_BUFSTRIDE;
        const char* vb = kb + A_VOFF;

        CP_WAIT0();
        if (tid < 64)
            *(float*)(smem + A_MSK + buf * 256 + tid * 4) = rmask ? 0.0f : -1e9f;
        if (t + 1 < SS / 64 && tid < 64)
            rmask = mask[b * SS + (t + 1) * 64 + tid];
        __syncthreads();

        // issue copy of tile t+1 (safe: all warps are past compute(t-1))
        if (t + 1 < SS / 64) {
            const uint32_t kd = sb + (buf ^ 1) * A_BUFSTRIDE;
            const char* gk = gkb + ((size_t)(t + 1) << 14);
#pragma unroll
            for (int i = 0; i < 4; ++i)
                cp16(kd + (tid + i * 256) * 16,
                     gk + (size_t)(tid + i * 256) * 16);
            const uint32_t vd = kd + A_VOFF;
            const char* gv = gvb + ((size_t)(t + 1) << 13);
#pragma unroll
            for (int i = 0; i < 2; ++i)
                cp16(vd + (tid + i * 256) * 16,
                     gv + (size_t)(tid + i * 256) * 16);
            CP_COMMIT();
        }

        // ---- scores (log2-domain): S = Q K^T via bf16 3-term ----
        float sc[8][4];
#pragma unroll
        for (int j = 0; j < 8; ++j)
#pragma unroll
            for (int e = 0; e < 4; ++e) sc[j][e] = 0.0f;
#pragma unroll
        for (int kt = 0; kt < 4; ++kt) {
#pragma unroll
            for (int j = 0; j < 8; ++j) {
                const uint4 k4v = *(const uint4*)(kb + (((kt * 8 + j) << 9) +
                                                       ((lane ^ kt) << 4)));
                uint32_t kh2[2] = {k4v.x, k4v.y};
                uint32_t kl2[2] = {k4v.z, k4v.w};
                mma_bf16(sc[j], qh[kt], kh2);
                mma_bf16(sc[j], qh[kt], kl2);
                mma_bf16(sc[j], ql[kt], kh2);
            }
        }

        // ---- mask, online softmax (log2-domain); overwrite sc with P ----
        const char* mbuf = smem + A_MSK + buf * 256;
#pragma unroll
        for (int j = 0; j < 8; ++j) {
            const float2 ma = *(const float2*)(mbuf + (j * 8 + 2 * tig) * 4);
            sc[j][0] += ma.x; sc[j][1] += ma.y;
            sc[j][2] += ma.x; sc[j][3] += ma.y;
        }
        float rm0 = -1e30f, rm1 = -1e30f;
#pragma unroll
        for (int j = 0; j < 8; ++j) {
            rm0 = fmaxf(rm0, fmaxf(sc[j][0], sc[j][1]));
            rm1 = fmaxf(rm1, fmaxf(sc[j][2], sc[j][3]));
        }
        rm0 = fmaxf(rm0, __shfl_xor_sync(0xFFFFFFFF, rm0, 1));
        rm0 = fmaxf(rm0, __shfl_xor_sync(0xFFFFFFFF, rm0, 2));
        rm1 = fmaxf(rm1, __shfl_xor_sync(0xFFFFFFFF, rm1, 1));
        rm1 = fmaxf(rm1, __shfl_xor_sync(0xFFFFFFFF, rm1, 2));
        const float nm0 = fmaxf(m0, rm0), nm1 = fmaxf(m1, rm1);
        const float c0 = ex2(m0 - nm0), c1 = ex2(m1 - nm1);
        m0 = nm0; m1 = nm1;
        l0 *= c0; l1 *= c1;
#pragma unroll
        for (int j = 0; j < 8; ++j) {
            o[j][0] *= c0; o[j][1] *= c0;
            o[j][2] *= c1; o[j][3] *= c1;
        }
        float s0 = 0.0f, s1 = 0.0f;
#pragma unroll
        for (int j = 0; j < 8; ++j) {
            const float p0 = ex2(sc[j][0] - nm0);
            const float p1 = ex2(sc[j][1] - nm0);
            const float p2 = ex2(sc[j][2] - nm1);
            const float p3 = ex2(sc[j][3] - nm1);
            s0 += p0 + p1; s1 += p2 + p3;
            sc[j][0] = p0; sc[j][1] = p1; sc[j][2] = p2; sc[j][3] = p3;
        }
        l0 += s0; l1 += s1;

        // ---- O += P V (fp16 k16; P direct from registers) ----
#pragma unroll
        for (int kk = 0; kk < 4; ++kk) {
            uint32_t pa[4];
            pa[0] = pack_f16x2(sc[2 * kk][0], sc[2 * kk][1]);
            pa[1] = pack_f16x2(sc[2 * kk][2], sc[2 * kk][3]);
            pa[2] = pack_f16x2(sc[2 * kk + 1][0], sc[2 * kk + 1][1]);
            pa[3] = pack_f16x2(sc[2 * kk + 1][2], sc[2 * kk + 1][3]);
#pragma unroll
            for (int j = 0; j < 8; ++j) {
                uint32_t bvf[2];
                const uint2 bv2 = *(const uint2*)(vb +
                    (((kk * 8 + j) * 32 + (lane ^ j)) << 3));
                bvf[0] = bv2.x; bvf[1] = bv2.y;
                mma_fp16(o[j], pa, bvf);
            }
        }
    }

    // ---- finalize ----
    float lt0 = l0, lt1 = l1;
    lt0 += __shfl_xor_sync(0xFFFFFFFF, lt0, 1);
    lt0 += __shfl_xor_sync(0xFFFFFFFF, lt0, 2);
    lt1 += __shfl_xor_sync(0xFFFFFFFF, lt1, 1);
    lt1 += __shfl_xor_sync(0xFFFFFFFF, lt1, 2);
    const float inv0 = 1.0f / lt0, inv1 = 1.0f / lt1;

    const int r0 = qs_base + gid, r1 = r0 + 8;
    float* o0 = g_ctx + ((size_t)(b * SS + r0)) * DD + h * DK;
    float* o1 = g_ctx + ((size_t)(b * SS + r1)) * DD + h * DK;
#pragma unroll
    for (int j = 0; j < 8; ++j) {
        const int cb = j * 8 + 2 * tig;
        float2 v0 = {o[j][0] * inv0, o[j][1] * inv0};
        float2 v1 = {o[j][2] * inv1, o[j][3] * inv1};
        *(float2*)(o0 + cb) = v0;
        *(float2*)(o1 + cb) = v1;
    }
}

// ---------------------------------------------------------------------------
// Inputs (metadata order): x, mask, Wq, bq, Wk, bk, Wv, bv, Wo, bo
// ---------------------------------------------------------------------------
extern "C" void kernel_launch(void* const* d_in, const int* in_sizes, int n_in,
                              void* d_out, int out_size) {
    const float* x  = (const float*)d_in[0];
    const int*   mk = (const int*)d_in[1];
    const float* Wq = (const float*)d_in[2];
    const float* bq = (const float*)d_in[3];
    const float* Wk = (const float*)d_in[4];
    const float* bk = (const float*)d_in[5];
    const float* Wv = (const float*)d_in[6];
    const float* bv = (const float*)d_in[7];
    const float* Wo = (const float*)d_in[8];
    const float* bo = (const float*)d_in[9];
    float* out = (float*)d_out;

    static bool configured = false;
    if (!configured) {
        cudaFuncSetAttribute(qkv_mm_kernel,
                             cudaFuncAttributeMaxDynamicSharedMemorySize,
                             MM_SMEM_BYTES);
        cudaFuncSetAttribute(oproj_mm_kernel,
                             cudaFuncAttributeMaxDynamicSharedMemorySize,
                             MM_SMEM_BYTES);
        cudaFuncSetAttribute(attn_kernel,
                             cudaFuncAttributeMaxDynamicSharedMemorySize,
                             ATTN_SMEM);
        configured = true;
    }

    // QKV projections (fp16 mma.sync); K/V written pre-packed for attention
    qkv_mm_kernel<<<dim3(DD / 128, MM / 128, 3), 256, MM_SMEM_BYTES>>>(
        x, Wq, bq, Wk, bk, Wv, bv);

    // Tensor-core flash attention (cp.async staging, 2 CTAs/SM)
    attn_kernel<<<dim3(SS / 128, BB * HH), 256, ATTN_SMEM>>>(mk);

    // Output projection (fp16 mma.sync) -> d_out
    oproj_mm_kernel<<<dim3(DD / 128, MM / 128), 256, MM_SMEM_BYTES>>>(Wo, bo, out);
}